// round 3
// baseline (speedup 1.0000x reference)
#include <cuda_runtime.h>
#include <cstdint>
#include <cstddef>

#define B_      64
#define LQ      1024
#define LK      1024
#define DH      64
#define QT      16
#define CHUNK   64
#define NCH     (LK / CHUNK)
#define KSP     68            // k smem pitch: (row*68+c) % 32 = (row*4+c)%32 -> conflict-free frags
#define SCP     1032          // sc pitch: (row*1032+col)%32 = (row*8+col)%32 -> conflict-free
#define TEMP_INV 0.125f
#define REMOVED  (-1.0e30f)
#define CUTV     (-1.0e29f)

#define SMEM_FLOATS (2 * CHUNK * KSP + QT * SCP)
#define SMEM_BYTES  (SMEM_FLOATS * 4)

#define KELEMS (B_ * LK * DH)          // 4,194,304

__device__ int   g_mask_kind;          // 0 = uint8/bool, 1 = int32, 2 = float32
__device__ float g_khi[KELEMS];        // K pre-split into tf32 hi/lo (computed every launch)
__device__ float g_klo[KELEMS];

// --------------------------------------------------------------------------
__global__ void detect_mask_kernel(const unsigned char* __restrict__ m) {
    __shared__ int nz[4];
    int tid = threadIdx.x;
    if (tid < 4) nz[tid] = 0;
    __syncthreads();
    int ph = tid & 3;
    int c = 0;
    for (int i = tid; i < 16384; i += 256)
        if (m[i]) c++;
    if (c) atomicAdd(&nz[ph], c);
    __syncthreads();
    if (tid == 0) {
        int kind;
        if ((nz[1] | nz[2] | nz[3]) == 0)      kind = 1;  // int32
        else if (nz[0] == 0 && nz[3] > 0)      kind = 2;  // float32
        else                                   kind = 0;  // uint8 / bool
        g_mask_kind = kind;
    }
}

__device__ __forceinline__ unsigned to_tf32(float x) {
    unsigned r;
    asm("cvt.rna.tf32.f32 %0, %1;" : "=r"(r) : "f"(x));
    return r;
}

// ---- one-time (per launch) K hi/lo tf32 split: 1 float4 per thread ----
__global__ void split_k_kernel(const float* __restrict__ k) {
    int i = blockIdx.x * 256 + threadIdx.x;        // float4 index
    float4 kv = ((const float4*)k)[i];
    float4 hi, lo;
    hi.x = __uint_as_float(to_tf32(kv.x));  lo.x = __uint_as_float(to_tf32(kv.x - hi.x));
    hi.y = __uint_as_float(to_tf32(kv.y));  lo.y = __uint_as_float(to_tf32(kv.y - hi.y));
    hi.z = __uint_as_float(to_tf32(kv.z));  lo.z = __uint_as_float(to_tf32(kv.z - hi.z));
    hi.w = __uint_as_float(to_tf32(kv.w));  lo.w = __uint_as_float(to_tf32(kv.w - hi.w));
    ((float4*)g_khi)[i] = hi;
    ((float4*)g_klo)[i] = lo;
}

__device__ __forceinline__ void mma_tf32(float& d0, float& d1, float& d2, float& d3,
                                         unsigned a0, unsigned a1, unsigned a2, unsigned a3,
                                         unsigned b0, unsigned b1) {
    asm("mma.sync.aligned.m16n8k8.row.col.f32.tf32.tf32.f32 "
        "{%0,%1,%2,%3}, {%4,%5,%6,%7}, {%8,%9}, {%0,%1,%2,%3};"
        : "+f"(d0), "+f"(d1), "+f"(d2), "+f"(d3)
        : "r"(a0), "r"(a1), "r"(a2), "r"(a3), "r"(b0), "r"(b1));
}

// --------------------------------------------------------------------------
// QK^T via 3xTF32 mma.sync (pre-split K) -> mask -> sparsemax -> sparse attn@V.
// One CTA = 16 q-rows of one batch. 8 warps; warp w owns score rows w, w+8
// and col-slice [w*8, w*8+8) of each 64-wide chunk.
// --------------------------------------------------------------------------
extern "C" __global__ void __launch_bounds__(256, 2)
sparse_attn_kernel(const float* __restrict__ q,
                   const float* __restrict__ v,
                   const void*  __restrict__ maskp,
                   float* __restrict__ out,
                   float* __restrict__ attn,
                   int write_attn)
{
    extern __shared__ float sm[];
    float* khi_s = sm;                         // [CHUNK][KSP]
    float* klo_s = sm + CHUNK * KSP;           // [CHUNK][KSP]
    float* sc    = sm + 2 * CHUNK * KSP;       // [QT][SCP]

    const int tid  = threadIdx.x;
    const int w    = tid >> 5;
    const int lane = tid & 31;
    const int b    = blockIdx.y;
    const int q0   = blockIdx.x * QT;
    const int mkind = g_mask_kind;

    // ---- A fragments (Q tile), hi/lo tf32 split, scaled ----
    unsigned ahi[8][4], alo[8][4];
    {
        const int ar0 = q0 + (lane >> 2);
        const float* qb0 = q + ((size_t)(b * LQ + ar0)) * DH + (lane & 3);
        const float* qb1 = qb0 + 8 * DH;
        #pragma unroll
        for (int ks = 0; ks < 8; ++ks) {
            float x0 = qb0[ks * 8]     * TEMP_INV;
            float x1 = qb1[ks * 8]     * TEMP_INV;
            float x2 = qb0[ks * 8 + 4] * TEMP_INV;
            float x3 = qb1[ks * 8 + 4] * TEMP_INV;
            unsigned h0 = to_tf32(x0), h1 = to_tf32(x1), h2 = to_tf32(x2), h3 = to_tf32(x3);
            ahi[ks][0] = h0; ahi[ks][1] = h1; ahi[ks][2] = h2; ahi[ks][3] = h3;
            alo[ks][0] = to_tf32(x0 - __uint_as_float(h0));
            alo[ks][1] = to_tf32(x1 - __uint_as_float(h1));
            alo[ks][2] = to_tf32(x2 - __uint_as_float(h2));
            alo[ks][3] = to_tf32(x3 - __uint_as_float(h3));
        }
    }

    // ---- QK^T over 16 chunks of 64 K-rows ----
    const int nb = w * 8;
    for (int c = 0; c < NCH; ++c) {
        __syncthreads();
        // stage pre-split K chunk (hi+lo): 64 rows x 16 float4 each
        {
            const float4* ghi = (const float4*)(g_khi + ((size_t)(b * LK + c * CHUNK)) * DH);
            const float4* glo = (const float4*)(g_klo + ((size_t)(b * LK + c * CHUNK)) * DH);
            #pragma unroll
            for (int it = 0; it < (CHUNK * 16) / 256; ++it) {
                int fi = tid + 256 * it;
                int r  = fi >> 4;
                int d4 = fi & 15;
                *(float4*)(khi_s + r * KSP + 4 * d4) = ghi[fi];
                *(float4*)(klo_s + r * KSP + 4 * d4) = glo[fi];
            }
        }
        __syncthreads();

        float d0 = 0.f, d1 = 0.f, d2 = 0.f, d3 = 0.f;
        const float* bph = khi_s + (nb + (lane >> 2)) * KSP + (lane & 3);
        const float* bpl = klo_s + (nb + (lane >> 2)) * KSP + (lane & 3);
        #pragma unroll
        for (int ks = 0; ks < 8; ++ks) {
            unsigned bh0 = __float_as_uint(bph[ks * 8]);
            unsigned bh1 = __float_as_uint(bph[ks * 8 + 4]);
            unsigned bl0 = __float_as_uint(bpl[ks * 8]);
            unsigned bl1 = __float_as_uint(bpl[ks * 8 + 4]);
            mma_tf32(d0, d1, d2, d3, ahi[ks][0], ahi[ks][1], ahi[ks][2], ahi[ks][3], bl0, bl1);
            mma_tf32(d0, d1, d2, d3, alo[ks][0], alo[ks][1], alo[ks][2], alo[ks][3], bh0, bh1);
            mma_tf32(d0, d1, d2, d3, ahi[ks][0], ahi[ks][1], ahi[ks][2], ahi[ks][3], bh0, bh1);
        }
        int row0 = lane >> 2;
        int gc   = c * CHUNK + nb + 2 * (lane & 3);
        *(float2*)(sc + row0 * SCP + gc)       = make_float2(d0, d1);
        *(float2*)(sc + (row0 + 8) * SCP + gc) = make_float2(d2, d3);
    }
    __syncthreads();

    // ---- mask pass, 16-byte vectorized loads ----
    {
        size_t mbase = ((size_t)b * LQ + q0) * LK;
        if (mkind == 0) {
            const uint4* m4 = (const uint4*)((const unsigned char*)maskp + mbase);
            #pragma unroll
            for (int it = 0; it < (QT * LK) / 16 / 256; ++it) {
                int idx  = tid + 256 * it;            // uint4 index within tile
                uint4 u  = m4[idx];
                int base = idx * 16;
                float* srow = sc + (base >> 10) * SCP + (base & 1023);
                #pragma unroll
                for (int bt = 0; bt < 4; ++bt) {
                    unsigned uu = (&u.x)[bt];
                    if (uu & 0x000000FFu) srow[bt * 4 + 0] = REMOVED;
                    if (uu & 0x0000FF00u) srow[bt * 4 + 1] = REMOVED;
                    if (uu & 0x00FF0000u) srow[bt * 4 + 2] = REMOVED;
                    if (uu & 0xFF000000u) srow[bt * 4 + 3] = REMOVED;
                }
            }
        } else {  // int32 / float32: nonzero bit pattern == true
            const uint4* m4 = (const uint4*)((const unsigned*)maskp + mbase);
            #pragma unroll
            for (int it = 0; it < (QT * LK) / 4 / 256; ++it) {
                int idx  = tid + 256 * it;            // uint4 index = 4 elems
                uint4 u  = m4[idx];
                int base = idx * 4;
                float* srow = sc + (base >> 10) * SCP + (base & 1023);
                if (u.x) srow[0] = REMOVED;
                if (u.y) srow[1] = REMOVED;
                if (u.z) srow[2] = REMOVED;
                if (u.w) srow[3] = REMOVED;
            }
        }
    }
    __syncthreads();

    // ---- sparsemax + sparse attn@V; warp w handles rows w and w+8 ----
    const float* vb = v + (size_t)b * LK * DH;
    #pragma unroll
    for (int rr = 0; rr < 2; ++rr) {
        const int row = w + 8 * rr;

        float z[32];
        #pragma unroll
        for (int t = 0; t < 32; ++t) z[t] = sc[row * SCP + lane + 32 * t];

        float S = 0.0f; int C = 0;
        #pragma unroll
        for (int t = 0; t < 32; ++t)
            if (z[t] > CUTV) { S += z[t]; C++; }
        #pragma unroll
        for (int o = 16; o; o >>= 1) {
            S += __shfl_xor_sync(0xFFFFFFFFu, S, o);
            C += __shfl_xor_sync(0xFFFFFFFFu, C, o);
        }

        float tau;
        if (C > 0) {
            tau = (S - 1.0f) / (float)C;
            // Michelot: remove-below-tau + recompute S,C in ONE pass/reduction per iter
            for (int iter = 0; iter < 64; ++iter) {
                float s2 = 0.0f; int c2 = 0;
                #pragma unroll
                for (int t = 0; t < 32; ++t) {
                    if (z[t] > CUTV) {
                        if (z[t] <= tau) z[t] = REMOVED;
                        else { s2 += z[t]; c2++; }
                    }
                }
                #pragma unroll
                for (int o = 16; o; o >>= 1) {
                    s2 += __shfl_xor_sync(0xFFFFFFFFu, s2, o);
                    c2 += __shfl_xor_sync(0xFFFFFFFFu, c2, o);
                }
                if (c2 == C) break;       // nothing removed -> converged
                S = s2; C = c2;
                tau = (S - 1.0f) / (float)C;
            }
        } else {
            tau = 1.0e30f;                // fully-masked row -> all zeros
        }

        // probabilities -> attn (direct, coalesced) + sparse V gather
        float2 acc2 = make_float2(0.0f, 0.0f);
        float* arow = attn + ((size_t)(b * LQ + q0 + row)) * LK;
        #pragma unroll
        for (int t = 0; t < 32; ++t) {
            float p = fmaxf(z[t] - tau, 0.0f);
            if (write_attn) arow[lane + 32 * t] = p;
            unsigned bal = __ballot_sync(0xFFFFFFFFu, p > 0.0f);
            while (bal) {
                int src = __ffs(bal) - 1;
                bal &= bal - 1;
                float pj = __shfl_sync(0xFFFFFFFFu, p, src);
                int j = src + 32 * t;
                const float2 vv = *(const float2*)(vb + (size_t)j * DH + 2 * lane);
                acc2.x += pj * vv.x;
                acc2.y += pj * vv.y;
            }
        }
        *(float2*)(out + ((size_t)(b * LQ + q0 + row)) * DH + 2 * lane) = acc2;
    }
}

// --------------------------------------------------------------------------
extern "C" void kernel_launch(void* const* d_in, const int* in_sizes, int n_in,
                              void* d_out, int out_size) {
    const float* q = (const float*)d_in[0];
    const float* k = (const float*)d_in[1];
    const float* v = (const float*)d_in[2];
    const void*  m = d_in[3];

    float* out = (float*)d_out;
    long long out_elems  = (long long)B_ * LQ * DH;
    long long attn_elems = (long long)B_ * LQ * LK;
    int write_attn = ((long long)out_size >= out_elems + attn_elems) ? 1 : 0;
    float* attn = out + (size_t)out_elems;

    detect_mask_kernel<<<1, 256>>>((const unsigned char*)m);
    split_k_kernel<<<KELEMS / 4 / 256, 256>>>(k);

    cudaFuncSetAttribute(sparse_attn_kernel,
                         cudaFuncAttributeMaxDynamicSharedMemorySize, SMEM_BYTES);

    dim3 grid(LQ / QT, B_);
    sparse_attn_kernel<<<grid, 256, SMEM_BYTES>>>(q, v, m, out, attn, write_attn);
}

// round 4
// speedup vs baseline: 1.7143x; 1.7143x over previous
#include <cuda_runtime.h>
#include <cstdint>
#include <cstddef>

#define B_      64
#define LQ      1024
#define LK      1024
#define DH      64
#define QT      16
#define CHUNK   128
#define NCH     (LK / CHUNK)
#define NTHR    512
#define KSP     68            // k smem pitch: (r*68+c)%32 = (4r+c)%32 -> conflict-free frags
#define SCP     1032          // sc pitch -> conflict-free epilogue
#define TEMP_INV 0.125f
#define REMOVED  (-1.0e30f)
#define CUTV     (-1.0e29f)

// smem floats: k_s[128*68] | a_s[8*2*32*4] | sc[16*1032]
#define AFRAG_FLOATS (8 * 2 * 32 * 4)
#define SMEM_FLOATS (CHUNK * KSP + AFRAG_FLOATS + QT * SCP)
#define SMEM_BYTES  (SMEM_FLOATS * 4)

__device__ int g_mask_kind;   // 0 = uint8/bool, 1 = int32, 2 = float32

__global__ void detect_mask_kernel(const unsigned char* __restrict__ m) {
    __shared__ int nz[4];
    int tid = threadIdx.x;
    if (tid < 4) nz[tid] = 0;
    __syncthreads();
    int ph = tid & 3;
    int c = 0;
    for (int i = tid; i < 16384; i += 256)
        if (m[i]) c++;
    if (c) atomicAdd(&nz[ph], c);
    __syncthreads();
    if (tid == 0) {
        int kind;
        if ((nz[1] | nz[2] | nz[3]) == 0)      kind = 1;  // int32
        else if (nz[0] == 0 && nz[3] > 0)      kind = 2;  // float32
        else                                   kind = 0;  // uint8 / bool
        g_mask_kind = kind;
    }
}

// Markidis truncation split: hi = x with low 13 mantissa bits cleared (valid tf32),
// lo = x - hi (exact; <=11 significant bits -> also valid tf32 bit pattern).
__device__ __forceinline__ float trunc_hi(float x) {
    return __uint_as_float(__float_as_uint(x) & 0xFFFFE000u);
}

__device__ __forceinline__ void mma_tf32(float& d0, float& d1, float& d2, float& d3,
                                         unsigned a0, unsigned a1, unsigned a2, unsigned a3,
                                         unsigned b0, unsigned b1) {
    asm("mma.sync.aligned.m16n8k8.row.col.f32.tf32.tf32.f32 "
        "{%0,%1,%2,%3}, {%4,%5,%6,%7}, {%8,%9}, {%0,%1,%2,%3};"
        : "+f"(d0), "+f"(d1), "+f"(d2), "+f"(d3)
        : "r"(a0), "r"(a1), "r"(a2), "r"(a3), "r"(b0), "r"(b1));
}

// --------------------------------------------------------------------------
// One CTA = 16 q-rows of one batch. 512 threads / 16 warps.
// GEMM: warp w owns cols [w*8, w*8+8) of each 128-wide chunk (3xTF32 mma).
// Sparsemax/V/attn: warp w owns score row w.
// --------------------------------------------------------------------------
extern "C" __global__ void __launch_bounds__(NTHR, 2)
sparse_attn_kernel(const float* __restrict__ q,
                   const float* __restrict__ k,
                   const float* __restrict__ v,
                   const void*  __restrict__ maskp,
                   float* __restrict__ out,
                   float* __restrict__ attn,
                   int write_attn)
{
    extern __shared__ float sm[];
    float* k_s = sm;                              // [CHUNK][KSP]
    float* a_s = sm + CHUNK * KSP;                // [8 ks][2 hi/lo][32 lane][4]
    float* sc  = a_s + AFRAG_FLOATS;              // [QT][SCP]

    const int tid  = threadIdx.x;
    const int w    = tid >> 5;
    const int lane = tid & 31;
    const int b    = blockIdx.y;
    const int q0   = blockIdx.x * QT;
    const int mkind = g_mask_kind;

    // ---- build A-fragment table in smem (once per CTA) ----
    // entry (ks, lane): j=0..3 -> A[r + (j&1)*8][ks*8 + c + (j>>1)*4], r=lane/4, c=lane%4
    for (int e = tid; e < 8 * 32; e += NTHR) {
        int ks = e >> 5, ln = e & 31;
        const float* qb = q + ((size_t)(b * LQ + q0 + (ln >> 2))) * DH + ks * 8 + (ln & 3);
        float x0 = qb[0]          * TEMP_INV;
        float x1 = qb[8 * DH]     * TEMP_INV;
        float x2 = qb[4]          * TEMP_INV;
        float x3 = qb[8 * DH + 4] * TEMP_INV;
        float4 hi, lo;
        hi.x = trunc_hi(x0); lo.x = x0 - hi.x;
        hi.y = trunc_hi(x1); lo.y = x1 - hi.y;
        hi.z = trunc_hi(x2); lo.z = x2 - hi.z;
        hi.w = trunc_hi(x3); lo.w = x3 - hi.w;
        *(float4*)(a_s + ((ks * 2 + 0) * 32 + ln) * 4) = hi;
        *(float4*)(a_s + ((ks * 2 + 1) * 32 + ln) * 4) = lo;
    }

    // ---- QK^T over 8 chunks of 128 K-rows ----
    const int nb = w * 8;
    for (int c = 0; c < NCH; ++c) {
        __syncthreads();
        // stage K chunk: 128 rows x 16 float4, coalesced
        #pragma unroll
        for (int it = 0; it < (CHUNK * 16) / NTHR; ++it) {
            int fi = tid + NTHR * it;
            int r  = fi >> 4;
            int d4 = fi & 15;
            const float4 kv = *(const float4*)(k + ((size_t)(b * LK + c * CHUNK + r)) * DH + 4 * d4);
            *(float4*)(k_s + r * KSP + 4 * d4) = kv;
        }
        __syncthreads();

        float d0 = 0.f, d1 = 0.f, d2 = 0.f, d3 = 0.f;
        const float* bp = k_s + (nb + (lane >> 2)) * KSP + (lane & 3);
        #pragma unroll
        for (int ks = 0; ks < 8; ++ks) {
            float b0f = bp[ks * 8];
            float b1f = bp[ks * 8 + 4];
            float bh0f = trunc_hi(b0f), bh1f = trunc_hi(b1f);
            unsigned bh0 = __float_as_uint(bh0f);
            unsigned bh1 = __float_as_uint(bh1f);
            unsigned bl0 = __float_as_uint(b0f - bh0f);
            unsigned bl1 = __float_as_uint(b1f - bh1f);
            const float4 ah = *(const float4*)(a_s + ((ks * 2 + 0) * 32 + lane) * 4);
            const float4 al = *(const float4*)(a_s + ((ks * 2 + 1) * 32 + lane) * 4);
            unsigned ah0 = __float_as_uint(ah.x), ah1 = __float_as_uint(ah.y),
                     ah2 = __float_as_uint(ah.z), ah3 = __float_as_uint(ah.w);
            mma_tf32(d0, d1, d2, d3, ah0, ah1, ah2, ah3, bl0, bl1);
            mma_tf32(d0, d1, d2, d3,
                     __float_as_uint(al.x), __float_as_uint(al.y),
                     __float_as_uint(al.z), __float_as_uint(al.w), bh0, bh1);
            mma_tf32(d0, d1, d2, d3, ah0, ah1, ah2, ah3, bh0, bh1);
        }
        int row0 = lane >> 2;
        int gc   = c * CHUNK + nb + 2 * (lane & 3);
        *(float2*)(sc + row0 * SCP + gc)       = make_float2(d0, d1);
        *(float2*)(sc + (row0 + 8) * SCP + gc) = make_float2(d2, d3);
    }
    __syncthreads();

    // ---- mask pass, 16-byte vectorized ----
    {
        size_t mbase = ((size_t)b * LQ + q0) * LK;
        if (mkind == 0) {
            const uint4* m4 = (const uint4*)((const unsigned char*)maskp + mbase);
            #pragma unroll
            for (int it = 0; it < (QT * LK) / 16 / NTHR; ++it) {
                int idx  = tid + NTHR * it;
                uint4 u  = m4[idx];
                int base = idx * 16;
                float* srow = sc + (base >> 10) * SCP + (base & 1023);
                #pragma unroll
                for (int bt = 0; bt < 4; ++bt) {
                    unsigned uu = (&u.x)[bt];
                    if (uu & 0x000000FFu) srow[bt * 4 + 0] = REMOVED;
                    if (uu & 0x0000FF00u) srow[bt * 4 + 1] = REMOVED;
                    if (uu & 0x00FF0000u) srow[bt * 4 + 2] = REMOVED;
                    if (uu & 0xFF000000u) srow[bt * 4 + 3] = REMOVED;
                }
            }
        } else {   // int32 / float32: nonzero bits == true
            const uint4* m4 = (const uint4*)((const unsigned*)maskp + mbase);
            #pragma unroll
            for (int it = 0; it < (QT * LK) / 4 / NTHR; ++it) {
                int idx  = tid + NTHR * it;
                uint4 u  = m4[idx];
                int base = idx * 4;
                float* srow = sc + (base >> 10) * SCP + (base & 1023);
                if (u.x) srow[0] = REMOVED;
                if (u.y) srow[1] = REMOVED;
                if (u.z) srow[2] = REMOVED;
                if (u.w) srow[3] = REMOVED;
            }
        }
    }
    __syncthreads();

    // ---- sparsemax (stateless Michelot: tau monotone => active set = {z > tau}) ----
    const int row = w;
    const float* zr = sc + row * SCP;

    float S = 0.0f; int C = 0;
    #pragma unroll
    for (int t4 = 0; t4 < 8; ++t4) {
        float4 zv = *(const float4*)(zr + 4 * lane + 128 * t4);
        if (zv.x > CUTV) { S += zv.x; C++; }
        if (zv.y > CUTV) { S += zv.y; C++; }
        if (zv.z > CUTV) { S += zv.z; C++; }
        if (zv.w > CUTV) { S += zv.w; C++; }
    }
    #pragma unroll
    for (int o = 16; o; o >>= 1) {
        S += __shfl_xor_sync(0xFFFFFFFFu, S, o);
        C += __shfl_xor_sync(0xFFFFFFFFu, C, o);
    }

    float tau;
    if (C > 0) {
        tau = (S - 1.0f) / (float)C;
        for (int iter = 0; iter < 64; ++iter) {
            float s2 = 0.0f; int c2 = 0;
            #pragma unroll
            for (int t4 = 0; t4 < 8; ++t4) {
                float4 zv = *(const float4*)(zr + 4 * lane + 128 * t4);
                if (zv.x > tau) { s2 += zv.x; c2++; }
                if (zv.y > tau) { s2 += zv.y; c2++; }
                if (zv.z > tau) { s2 += zv.z; c2++; }
                if (zv.w > tau) { s2 += zv.w; c2++; }
            }
            #pragma unroll
            for (int o = 16; o; o >>= 1) {
                s2 += __shfl_xor_sync(0xFFFFFFFFu, s2, o);
                c2 += __shfl_xor_sync(0xFFFFFFFFu, c2, o);
            }
            if (c2 == C) break;           // converged (nothing removed)
            S = s2; C = c2;
            tau = (S - 1.0f) / (float)C;
        }
    } else {
        tau = 1.0e30f;                    // fully-masked row -> all zeros
    }

    // ---- probabilities -> attn (direct) + sparse attn@V ----
    const float* vb = v + (size_t)b * LK * DH;
    float2 acc2 = make_float2(0.0f, 0.0f);
    float* arow = attn + ((size_t)(b * LQ + q0 + row)) * LK;
    #pragma unroll
    for (int t = 0; t < 32; ++t) {
        float p = fmaxf(zr[lane + 32 * t] - tau, 0.0f);
        if (write_attn) arow[lane + 32 * t] = p;
        unsigned bal = __ballot_sync(0xFFFFFFFFu, p > 0.0f);
        while (bal) {
            int src = __ffs(bal) - 1;
            bal &= bal - 1;
            float pj = __shfl_sync(0xFFFFFFFFu, p, src);
            int j = src + 32 * t;
            const float2 vv = *(const float2*)(vb + (size_t)j * DH + 2 * lane);
            acc2.x += pj * vv.x;
            acc2.y += pj * vv.y;
        }
    }
    *(float2*)(out + ((size_t)(b * LQ + q0 + row)) * DH + 2 * lane) = acc2;
}

// --------------------------------------------------------------------------
extern "C" void kernel_launch(void* const* d_in, const int* in_sizes, int n_in,
                              void* d_out, int out_size) {
    const float* q = (const float*)d_in[0];
    const float* k = (const float*)d_in[1];
    const float* v = (const float*)d_in[2];
    const void*  m = d_in[3];

    float* out = (float*)d_out;
    long long out_elems  = (long long)B_ * LQ * DH;
    long long attn_elems = (long long)B_ * LQ * LK;
    int write_attn = ((long long)out_size >= out_elems + attn_elems) ? 1 : 0;
    float* attn = out + (size_t)out_elems;

    detect_mask_kernel<<<1, 256>>>((const unsigned char*)m);

    cudaFuncSetAttribute(sparse_attn_kernel,
                         cudaFuncAttributeMaxDynamicSharedMemorySize, SMEM_BYTES);

    dim3 grid(LQ / QT, B_);
    sparse_attn_kernel<<<grid, NTHR, SMEM_BYTES>>>(q, k, v, m, out, attn, write_attn);
}